// round 9
// baseline (speedup 1.0000x reference)
#include <cuda_runtime.h>
#include <cstdint>

// Batched GEMM out[b,n,m] = sum_e A[b,n,e]*B[b,m,e]; b=8, n=m=2048, e=1024, fp32.
// mma.sync.m16n8k8 tf32. 256 threads, 8 warps (4x2), warp tile 32x64,
// CTA tile 128x128, BK=32, 2-stage cp.async double buffer, cvt.rna after LDS.
// Target: 2 CTAs/SM so one CTA's MMAs cover the other's produce/barrier bubble.

#define THREADS 256
#define BM 128            // n-rows per CTA
#define BN 128            // m-cols per CTA
#define BK 32             // k floats per stage (128 bytes)
#define E_DIM 1024
#define SEQ 2048
#define NSTAGE (E_DIM / BK)     // 32

#define ROWB 144                 // padded smem row stride (bytes)
#define A_BYTES (BM * ROWB)      // 18432
#define B_BYTES (BN * ROWB)      // 18432
#define STAGE_BYTES (A_BYTES + B_BYTES)   // 36864
#define SMEM_TOTAL (2 * STAGE_BYTES)      // 73728

__device__ __forceinline__ uint32_t smem_u32(const void* p) {
    uint32_t a;
    asm("{ .reg .u64 t; cvta.to.shared.u64 t, %1; cvt.u32.u64 %0, t; }" : "=r"(a) : "l"(p));
    return a;
}

__device__ __forceinline__ uint32_t f2tf32(float f) {
    uint32_t r;
    asm("cvt.rna.tf32.f32 %0, %1;" : "=r"(r) : "f"(f));
    return r;
}

__device__ __forceinline__ uint32_t lds_tf32(uint32_t a) {
    float v;
    asm volatile("ld.shared.b32 %0, [%1];" : "=f"(v) : "r"(a));
    return f2tf32(v);
}

__device__ __forceinline__ void cp_async16(uint32_t dst, const void* src) {
    asm volatile("cp.async.cg.shared.global [%0], [%1], 16;"
                 :: "r"(dst), "l"(src) : "memory");
}

__device__ __forceinline__ void cp_commit() {
    asm volatile("cp.async.commit_group;" ::: "memory");
}

__device__ __forceinline__ void cp_wait0() {
    asm volatile("cp.async.wait_group 0;" ::: "memory");
}

__device__ __forceinline__ void mma_tf32(float c[4], uint32_t a0, uint32_t a1,
                                         uint32_t a2, uint32_t a3,
                                         uint32_t b0, uint32_t b1) {
    asm volatile(
        "mma.sync.aligned.m16n8k8.row.col.f32.tf32.tf32.f32 "
        "{%0,%1,%2,%3}, {%4,%5,%6,%7}, {%8,%9}, {%0,%1,%2,%3};"
        : "+f"(c[0]), "+f"(c[1]), "+f"(c[2]), "+f"(c[3])
        : "r"(a0), "r"(a1), "r"(a2), "r"(a3), "r"(b0), "r"(b1));
}

extern "C" __global__ void __launch_bounds__(THREADS, 2)
attn_matrix_mma_kernel(const float* __restrict__ A0,
                       const float* __restrict__ B0,
                       float* __restrict__ out) {
    extern __shared__ char smem[];
    const uint32_t sbase = smem_u32(smem);
    const int tid  = threadIdx.x;
    const int wid  = tid >> 5;
    const int lane = tid & 31;
    const int g    = lane >> 2;   // 0..7
    const int tig  = lane & 3;    // 0..3
    const int wn   = wid >> 1;    // 0..3 : 32 n-rows each
    const int wm   = wid & 1;     // 0..1 : 64 m-cols each

    const int mtile = blockIdx.x;          // over m (BN)
    const int ntile = blockIdx.y;          // over n (BM)
    const int b     = blockIdx.z;
    const long nbase = (long)ntile * BM;
    const long mbase = (long)mtile * BN;
    const float* Ap = A0 + ((long)b * SEQ + nbase) * E_DIM;
    const float* Bp = B0 + ((long)b * SEQ + mbase) * E_DIM;

    // producer lanes: row = tid>>3 (0..31), 16B chunk q = tid&7; 4 row-groups of 32
    const int lrow = tid >> 3;
    const int lq   = tid & 7;
    const float* gA = Ap + (long)lrow * E_DIM + lq * 4;
    const float* gB = Bp + (long)lrow * E_DIM + lq * 4;
    const uint32_t stsA = sbase + (uint32_t)(lrow * ROWB + lq * 16);
    const uint32_t stsB = stsA + A_BYTES;

    // fragment LDS bases (stage 0)
    const uint32_t ldsA0 = sbase + (uint32_t)((wn * 32 + g) * ROWB + tig * 4);
    const uint32_t ldsB0 = sbase + A_BYTES + (uint32_t)((wm * 64 + g) * ROWB + tig * 4);

    float acc[2][8][4];
    #pragma unroll
    for (int i = 0; i < 2; i++)
        #pragma unroll
        for (int j = 0; j < 8; j++)
            #pragma unroll
            for (int k = 0; k < 4; k++) acc[i][j][k] = 0.f;

    // ---- prologue: stage 0 via cp.async ----
    #pragma unroll
    for (int t = 0; t < 4; t++) {
        cp_async16(stsA + (uint32_t)(t * 32 * ROWB), gA + (long)t * 32 * E_DIM);
        cp_async16(stsB + (uint32_t)(t * 32 * ROWB), gB + (long)t * 32 * E_DIM);
    }
    cp_commit();

    // ---- main loop ----
    for (int ks = 0; ks < NSTAGE; ks++) {
        const int buf = ks & 1;
        cp_wait0();
        __syncthreads();

        // issue next stage loads into the other buffer (overlap with compute)
        if (ks + 1 < NSTAGE) {
            const uint32_t nb = (uint32_t)((buf ^ 1) * STAGE_BYTES);
            const int k0 = (ks + 1) * BK;
            #pragma unroll
            for (int t = 0; t < 4; t++) {
                cp_async16(stsA + nb + (uint32_t)(t * 32 * ROWB),
                           gA + (long)t * 32 * E_DIM + k0);
                cp_async16(stsB + nb + (uint32_t)(t * 32 * ROWB),
                           gB + (long)t * 32 * E_DIM + k0);
            }
            cp_commit();
        }

        const uint32_t aB = ldsA0 + (uint32_t)(buf * STAGE_BYTES);
        const uint32_t bB = ldsB0 + (uint32_t)(buf * STAGE_BYTES);

        #pragma unroll
        for (int kk = 0; kk < 4; kk++) {
            uint32_t a[2][4], bb[8][2];
            #pragma unroll
            for (int mi = 0; mi < 2; mi++) {
                const uint32_t r = aB + (uint32_t)(mi * 16 * ROWB + kk * 32);
                a[mi][0] = lds_tf32(r);
                a[mi][1] = lds_tf32(r + 8 * ROWB);
                a[mi][2] = lds_tf32(r + 16);
                a[mi][3] = lds_tf32(r + 8 * ROWB + 16);
            }
            #pragma unroll
            for (int ni = 0; ni < 8; ni++) {
                const uint32_t r = bB + (uint32_t)(ni * 8 * ROWB + kk * 32);
                bb[ni][0] = lds_tf32(r);
                bb[ni][1] = lds_tf32(r + 16);
            }
            #pragma unroll
            for (int mi = 0; mi < 2; mi++)
                #pragma unroll
                for (int ni = 0; ni < 8; ni++)
                    mma_tf32(acc[mi][ni], a[mi][0], a[mi][1], a[mi][2], a[mi][3],
                             bb[ni][0], bb[ni][1]);
        }
        __syncthreads();
    }

    // ---- epilogue ----
    const int orow = (int)nbase + wn * 32 + g;
    const int ocol = (int)mbase + wm * 64 + tig * 2;
    float* ob = out + (long)b * SEQ * SEQ;
    #pragma unroll
    for (int mi = 0; mi < 2; mi++) {
        #pragma unroll
        for (int ni = 0; ni < 8; ni++) {
            const long r0 = (long)(orow + mi * 16) * SEQ;
            *(float2*)(ob + r0 + ocol + ni * 8) =
                make_float2(acc[mi][ni][0], acc[mi][ni][1]);
            *(float2*)(ob + r0 + 8 * SEQ + ocol + ni * 8) =
                make_float2(acc[mi][ni][2], acc[mi][ni][3]);
        }
    }
}

extern "C" void kernel_launch(void* const* d_in, const int* in_sizes, int n_in,
                              void* d_out, int out_size) {
    const float* a = (const float*)d_in[0];   // mat_0 [8, 2048, 1024]
    const float* b = (const float*)d_in[1];   // mat_1 [8, 2048, 1024]
    float* o = (float*)d_out;                 // out   [8, 2048, 2048]

    cudaFuncSetAttribute(attn_matrix_mma_kernel,
                         cudaFuncAttributeMaxDynamicSharedMemorySize, SMEM_TOTAL);
    dim3 grid(SEQ / BN, SEQ / BM, 8);         // (16, 16, 8) = 2048 CTAs
    attn_matrix_mma_kernel<<<grid, THREADS, SMEM_TOTAL>>>(a, b, o);
}

// round 10
// speedup vs baseline: 1.0273x; 1.0273x over previous
#include <cuda_runtime.h>
#include <cstdint>

// Batched GEMM out[b,n,m] = sum_e A[b,n,e]*B[b,m,e]; b=8, n=m=2048, e=1024, fp32.
// mma.sync.m16n8k8 tf32. 256 threads, 8 warps (2x4), warp tile 64x64,
// CTA tile 128x256, BK=32, 3-stage cp.async ring (raw fp32), cvt.rna after LDS.

#define THREADS 256
#define BM 128            // n-rows per CTA
#define BN 256            // m-cols per CTA
#define BK 32             // k floats per stage (128 bytes)
#define E_DIM 1024
#define SEQ 2048
#define NSTAGE (E_DIM / BK)     // 32
#define STAGES 3

#define ROWB 144                 // padded smem row stride (bytes)
#define A_BYTES (BM * ROWB)      // 18432
#define B_BYTES (BN * ROWB)      // 36864
#define STAGE_BYTES (A_BYTES + B_BYTES)   // 55296
#define SMEM_TOTAL (STAGES * STAGE_BYTES) // 165888

__device__ __forceinline__ uint32_t smem_u32(const void* p) {
    uint32_t a;
    asm("{ .reg .u64 t; cvta.to.shared.u64 t, %1; cvt.u32.u64 %0, t; }" : "=r"(a) : "l"(p));
    return a;
}

__device__ __forceinline__ uint32_t f2tf32(float f) {
    uint32_t r;
    asm("cvt.rna.tf32.f32 %0, %1;" : "=r"(r) : "f"(f));
    return r;
}

__device__ __forceinline__ uint32_t lds_tf32(uint32_t a) {
    float v;
    asm volatile("ld.shared.b32 %0, [%1];" : "=f"(v) : "r"(a));
    return f2tf32(v);
}

__device__ __forceinline__ void cp_async16(uint32_t dst, const void* src) {
    asm volatile("cp.async.cg.shared.global [%0], [%1], 16;"
                 :: "r"(dst), "l"(src) : "memory");
}

__device__ __forceinline__ void cp_commit() {
    asm volatile("cp.async.commit_group;" ::: "memory");
}

template <int N>
__device__ __forceinline__ void cp_wait() {
    asm volatile("cp.async.wait_group %0;" :: "n"(N) : "memory");
}

__device__ __forceinline__ void mma_tf32(float c[4], uint32_t a0, uint32_t a1,
                                         uint32_t a2, uint32_t a3,
                                         uint32_t b0, uint32_t b1) {
    asm volatile(
        "mma.sync.aligned.m16n8k8.row.col.f32.tf32.tf32.f32 "
        "{%0,%1,%2,%3}, {%4,%5,%6,%7}, {%8,%9}, {%0,%1,%2,%3};"
        : "+f"(c[0]), "+f"(c[1]), "+f"(c[2]), "+f"(c[3])
        : "r"(a0), "r"(a1), "r"(a2), "r"(a3), "r"(b0), "r"(b1));
}

extern "C" __global__ void __launch_bounds__(THREADS)
attn_matrix_mma_kernel(const float* __restrict__ A0,
                       const float* __restrict__ B0,
                       float* __restrict__ out) {
    extern __shared__ char smem[];
    const uint32_t sbase = smem_u32(smem);
    const int tid  = threadIdx.x;
    const int wid  = tid >> 5;
    const int lane = tid & 31;
    const int g    = lane >> 2;   // 0..7
    const int tig  = lane & 3;    // 0..3
    const int wn   = wid >> 2;    // 0..1 : 64 n-rows each
    const int wm   = wid & 3;     // 0..3 : 64 m-cols each

    const int mtile = blockIdx.x;          // over m (BN)
    const int ntile = blockIdx.y;          // over n (BM)
    const int b     = blockIdx.z;
    const long nbase = (long)ntile * BM;
    const long mbase = (long)mtile * BN;
    const float* Ap = A0 + ((long)b * SEQ + nbase) * E_DIM;
    const float* Bp = B0 + ((long)b * SEQ + mbase) * E_DIM;

    // producer lanes: row = tid>>3 (0..31), 16B chunk q = tid&7
    const int lrow = tid >> 3;
    const int lq   = tid & 7;
    const float* gA = Ap + (long)lrow * E_DIM + lq * 4;
    const float* gB = Bp + (long)lrow * E_DIM + lq * 4;
    const uint32_t stsA = sbase + (uint32_t)(lrow * ROWB + lq * 16);
    const uint32_t stsB = stsA + A_BYTES;

    // fragment LDS bases (stage 0)
    const uint32_t ldsA0 = sbase + (uint32_t)((wn * 64 + g) * ROWB + tig * 4);
    const uint32_t ldsB0 = sbase + A_BYTES + (uint32_t)((wm * 64 + g) * ROWB + tig * 4);

    float acc[4][8][4];
    #pragma unroll
    for (int i = 0; i < 4; i++)
        #pragma unroll
        for (int j = 0; j < 8; j++)
            #pragma unroll
            for (int k = 0; k < 4; k++) acc[i][j][k] = 0.f;

    // ---- prologue: issue stages 0..STAGES-2 ----
    #pragma unroll
    for (int s = 0; s < STAGES - 1; s++) {
        const uint32_t sb = (uint32_t)(s * STAGE_BYTES);
        const int k0 = s * BK;
        #pragma unroll
        for (int t = 0; t < 4; t++)
            cp_async16(stsA + sb + (uint32_t)(t * 32 * ROWB),
                       gA + (long)t * 32 * E_DIM + k0);
        #pragma unroll
        for (int t = 0; t < 8; t++)
            cp_async16(stsB + sb + (uint32_t)(t * 32 * ROWB),
                       gB + (long)t * 32 * E_DIM + k0);
        cp_commit();
    }

    // ---- main loop ----
    int buf = 0;
    for (int ks = 0; ks < NSTAGE; ks++) {
        cp_wait<STAGES - 2>();      // stage-ks group complete
        __syncthreads();            // all warps done with the buffer being refilled

        // issue stage ks+STAGES-1 into buffer (ks-1)%STAGES — overlaps compute
        if (ks + STAGES - 1 < NSTAGE) {
            const int s = ks + STAGES - 1;
            const uint32_t sb = (uint32_t)((s % STAGES) * STAGE_BYTES);
            const int k0 = s * BK;
            #pragma unroll
            for (int t = 0; t < 4; t++)
                cp_async16(stsA + sb + (uint32_t)(t * 32 * ROWB),
                           gA + (long)t * 32 * E_DIM + k0);
            #pragma unroll
            for (int t = 0; t < 8; t++)
                cp_async16(stsB + sb + (uint32_t)(t * 32 * ROWB),
                           gB + (long)t * 32 * E_DIM + k0);
            cp_commit();
        }

        const uint32_t aB = ldsA0 + (uint32_t)(buf * STAGE_BYTES);
        const uint32_t bB = ldsB0 + (uint32_t)(buf * STAGE_BYTES);

        #pragma unroll
        for (int kk = 0; kk < 4; kk++) {
            uint32_t a[4][4], bb[8][2];
            #pragma unroll
            for (int mi = 0; mi < 4; mi++) {
                const uint32_t r = aB + (uint32_t)(mi * 16 * ROWB + kk * 32);
                a[mi][0] = lds_tf32(r);
                a[mi][1] = lds_tf32(r + 8 * ROWB);
                a[mi][2] = lds_tf32(r + 16);
                a[mi][3] = lds_tf32(r + 8 * ROWB + 16);
            }
            #pragma unroll
            for (int ni = 0; ni < 8; ni++) {
                const uint32_t r = bB + (uint32_t)(ni * 8 * ROWB + kk * 32);
                bb[ni][0] = lds_tf32(r);
                bb[ni][1] = lds_tf32(r + 16);
            }
            #pragma unroll
            for (int mi = 0; mi < 4; mi++)
                #pragma unroll
                for (int ni = 0; ni < 8; ni++)
                    mma_tf32(acc[mi][ni], a[mi][0], a[mi][1], a[mi][2], a[mi][3],
                             bb[ni][0], bb[ni][1]);
        }

        buf = (buf + 1 == STAGES) ? 0 : buf + 1;
    }

    // ---- epilogue ----
    const int orow = (int)nbase + wn * 64 + g;
    const int ocol = (int)mbase + wm * 64 + tig * 2;
    float* ob = out + (long)b * SEQ * SEQ;
    #pragma unroll
    for (int mi = 0; mi < 4; mi++) {
        #pragma unroll
        for (int ni = 0; ni < 8; ni++) {
            const long r0 = (long)(orow + mi * 16) * SEQ;
            *(float2*)(ob + r0 + ocol + ni * 8) =
                make_float2(acc[mi][ni][0], acc[mi][ni][1]);
            *(float2*)(ob + r0 + 8 * SEQ + ocol + ni * 8) =
                make_float2(acc[mi][ni][2], acc[mi][ni][3]);
        }
    }
}

extern "C" void kernel_launch(void* const* d_in, const int* in_sizes, int n_in,
                              void* d_out, int out_size) {
    const float* a = (const float*)d_in[0];   // mat_0 [8, 2048, 1024]
    const float* b = (const float*)d_in[1];   // mat_1 [8, 2048, 1024]
    float* o = (float*)d_out;                 // out   [8, 2048, 2048]

    cudaFuncSetAttribute(attn_matrix_mma_kernel,
                         cudaFuncAttributeMaxDynamicSharedMemorySize, SMEM_TOTAL);
    dim3 grid(SEQ / BN, SEQ / BM, 8);         // (8, 16, 8) = 1024 CTAs
    attn_matrix_mma_kernel<<<grid, THREADS, SMEM_TOTAL>>>(a, b, o);
}

// round 11
// speedup vs baseline: 1.8227x; 1.7743x over previous
#include <cuda_runtime.h>
#include <cstdint>

// Batched GEMM out[b,n,m] = sum_e A[b,n,e]*B[b,m,e]; b=8, n=m=2048, e=1024, fp32.
// mma.sync.m16n8k16 fp16 (f32 accum). 256 threads, 8 warps (2x4), warp tile 64x64,
// CTA tile 128x256, BK=32 floats (2 k16 steps), 2-stage smem double buffer,
// cvt.rn.f16x2 on the producer path (only rounding = input cvt, same as tf32).

#define THREADS 256
#define BM 128            // n-rows per CTA
#define BN 256            // m-cols per CTA
#define BK 32             // k floats per stage
#define E_DIM 1024
#define SEQ 2048
#define NSTAGE (E_DIM / BK)     // 32

#define ROWB 80                  // padded smem row stride (bytes); 32 halfs = 64B data
#define A_BYTES (BM * ROWB)      // 10240
#define B_BYTES (BN * ROWB)      // 20480
#define STAGE_BYTES (A_BYTES + B_BYTES)   // 30720
#define SMEM_TOTAL (2 * STAGE_BYTES)      // 61440

__device__ __forceinline__ uint32_t smem_u32(const void* p) {
    uint32_t a;
    asm("{ .reg .u64 t; cvta.to.shared.u64 t, %1; cvt.u32.u64 %0, t; }" : "=r"(a) : "l"(p));
    return a;
}

// pack two fp32 -> f16x2 (lo = x, hi = y), round-to-nearest-even
__device__ __forceinline__ uint32_t pack_f16x2(float x, float y) {
    uint32_t r;
    asm("cvt.rn.f16x2.f32 %0, %1, %2;" : "=r"(r) : "f"(y), "f"(x));
    return r;
}

__device__ __forceinline__ void sts64(uint32_t a, uint32_t r0, uint32_t r1) {
    asm volatile("st.shared.v2.b32 [%0], {%1,%2};"
                 :: "r"(a), "r"(r0), "r"(r1) : "memory");
}

__device__ __forceinline__ uint32_t lds32(uint32_t a) {
    uint32_t v;
    asm volatile("ld.shared.b32 %0, [%1];" : "=r"(v) : "r"(a));
    return v;
}

__device__ __forceinline__ void mma_f16(float c[4], uint32_t a0, uint32_t a1,
                                        uint32_t a2, uint32_t a3,
                                        uint32_t b0, uint32_t b1) {
    asm volatile(
        "mma.sync.aligned.m16n8k16.row.col.f32.f16.f16.f32 "
        "{%0,%1,%2,%3}, {%4,%5,%6,%7}, {%8,%9}, {%0,%1,%2,%3};"
        : "+f"(c[0]), "+f"(c[1]), "+f"(c[2]), "+f"(c[3])
        : "r"(a0), "r"(a1), "r"(a2), "r"(a3), "r"(b0), "r"(b1));
}

extern "C" __global__ void __launch_bounds__(THREADS)
attn_matrix_mma_kernel(const float* __restrict__ A0,
                       const float* __restrict__ B0,
                       float* __restrict__ out) {
    extern __shared__ char smem[];
    const uint32_t sbase = smem_u32(smem);
    const int tid  = threadIdx.x;
    const int wid  = tid >> 5;
    const int lane = tid & 31;
    const int g    = lane >> 2;   // 0..7
    const int tig  = lane & 3;    // 0..3
    const int wn   = wid >> 2;    // 0..1 : 64 n-rows each
    const int wm   = wid & 3;     // 0..3 : 64 m-cols each

    const int mtile = blockIdx.x;          // over m (BN)
    const int ntile = blockIdx.y;          // over n (BM)
    const int b     = blockIdx.z;
    const long nbase = (long)ntile * BM;
    const long mbase = (long)mtile * BN;
    const float* Ap = A0 + ((long)b * SEQ + nbase) * E_DIM;
    const float* Bp = B0 + ((long)b * SEQ + mbase) * E_DIM;

    // producer lanes: row = tid>>3 (0..31), 16B fp32 chunk q = tid&7
    const int lrow = tid >> 3;
    const int lq   = tid & 7;
    const float* gA = Ap + (long)lrow * E_DIM + lq * 4;
    const float* gB = Bp + (long)lrow * E_DIM + lq * 4;
    // f16 dest: 4 floats -> 2 b32 = 8 bytes at (row, lq*8)
    const uint32_t stsA = sbase + (uint32_t)(lrow * ROWB + lq * 8);
    const uint32_t stsB = stsA + A_BYTES;

    // fragment LDS bases (stage 0): k-halfs contiguous, b32 = 2 halfs
    const uint32_t ldsA0 = sbase + (uint32_t)((wn * 64 + g) * ROWB + tig * 4);
    const uint32_t ldsB0 = sbase + A_BYTES + (uint32_t)((wm * 64 + g) * ROWB + tig * 4);

    float acc[4][8][4];
    #pragma unroll
    for (int i = 0; i < 4; i++)
        #pragma unroll
        for (int j = 0; j < 8; j++)
            #pragma unroll
            for (int k = 0; k < 4; k++) acc[i][j][k] = 0.f;

    // ---- prologue: fill stage 0 ----
    {
        #pragma unroll
        for (int t = 0; t < 4; t++) {              // A: 128 rows, 32/iter
            float4 v = *(const float4*)(gA + (long)t * 32 * E_DIM);
            sts64(stsA + (uint32_t)(t * 32 * ROWB),
                  pack_f16x2(v.x, v.y), pack_f16x2(v.z, v.w));
        }
        #pragma unroll
        for (int t = 0; t < 8; t++) {              // B: 256 rows
            float4 v = *(const float4*)(gB + (long)t * 32 * E_DIM);
            sts64(stsB + (uint32_t)(t * 32 * ROWB),
                  pack_f16x2(v.x, v.y), pack_f16x2(v.z, v.w));
        }
    }
    __syncthreads();

    // ---- main loop ----
    for (int ks = 0; ks < NSTAGE; ks++) {
        const int buf = ks & 1;
        const uint32_t aB = ldsA0 + (uint32_t)(buf * STAGE_BYTES);
        const uint32_t bB = ldsB0 + (uint32_t)(buf * STAGE_BYTES);

        // prefetch next stage into registers
        float4 pfA[4], pfB[8];
        const bool pf = (ks + 1 < NSTAGE);
        if (pf) {
            const float* ga = gA + (ks + 1) * BK;
            const float* gb = gB + (ks + 1) * BK;
            #pragma unroll
            for (int t = 0; t < 4; t++) pfA[t] = *(const float4*)(ga + (long)t * 32 * E_DIM);
            #pragma unroll
            for (int t = 0; t < 8; t++) pfB[t] = *(const float4*)(gb + (long)t * 32 * E_DIM);
        }

        // 2 k16 steps cover the 32-float chunk
        #pragma unroll
        for (int kk = 0; kk < 2; kk++) {
            uint32_t a[4][4], bb[8][2];
            #pragma unroll
            for (int mi = 0; mi < 4; mi++) {
                const uint32_t r = aB + (uint32_t)(mi * 16 * ROWB + kk * 32);
                a[mi][0] = lds32(r);                  // row g,   k 2tig..+1
                a[mi][1] = lds32(r + 8 * ROWB);       // row g+8
                a[mi][2] = lds32(r + 16);             // row g,   k +8
                a[mi][3] = lds32(r + 8 * ROWB + 16);  // row g+8, k +8
            }
            #pragma unroll
            for (int ni = 0; ni < 8; ni++) {
                const uint32_t r = bB + (uint32_t)(ni * 8 * ROWB + kk * 32);
                bb[ni][0] = lds32(r);                 // col g, k 2tig..+1
                bb[ni][1] = lds32(r + 16);            // col g, k +8
            }
            #pragma unroll
            for (int mi = 0; mi < 4; mi++)
                #pragma unroll
                for (int ni = 0; ni < 8; ni++)
                    mma_f16(acc[mi][ni], a[mi][0], a[mi][1], a[mi][2], a[mi][3],
                            bb[ni][0], bb[ni][1]);
        }

        if (pf) {
            const uint32_t nb = (uint32_t)((buf ^ 1) * STAGE_BYTES);
            #pragma unroll
            for (int t = 0; t < 4; t++)
                sts64(stsA + nb + (uint32_t)(t * 32 * ROWB),
                      pack_f16x2(pfA[t].x, pfA[t].y), pack_f16x2(pfA[t].z, pfA[t].w));
            #pragma unroll
            for (int t = 0; t < 8; t++)
                sts64(stsB + nb + (uint32_t)(t * 32 * ROWB),
                      pack_f16x2(pfB[t].x, pfB[t].y), pack_f16x2(pfB[t].z, pfB[t].w));
        }
        __syncthreads();
    }

    // ---- epilogue (C layout identical to m16n8k8) ----
    const int orow = (int)nbase + wn * 64 + g;
    const int ocol = (int)mbase + wm * 64 + tig * 2;
    float* ob = out + (long)b * SEQ * SEQ;
    #pragma unroll
    for (int mi = 0; mi < 4; mi++) {
        #pragma unroll
        for (int ni = 0; ni < 8; ni++) {
            const long r0 = (long)(orow + mi * 16) * SEQ;
            *(float2*)(ob + r0 + ocol + ni * 8) =
                make_float2(acc[mi][ni][0], acc[mi][ni][1]);
            *(float2*)(ob + r0 + 8 * SEQ + ocol + ni * 8) =
                make_float2(acc[mi][ni][2], acc[mi][ni][3]);
        }
    }
}

extern "C" void kernel_launch(void* const* d_in, const int* in_sizes, int n_in,
                              void* d_out, int out_size) {
    const float* a = (const float*)d_in[0];   // mat_0 [8, 2048, 1024]
    const float* b = (const float*)d_in[1];   // mat_1 [8, 2048, 1024]
    float* o = (float*)d_out;                 // out   [8, 2048, 2048]

    cudaFuncSetAttribute(attn_matrix_mma_kernel,
                         cudaFuncAttributeMaxDynamicSharedMemorySize, SMEM_TOTAL);
    dim3 grid(SEQ / BN, SEQ / BM, 8);         // (8, 16, 8) = 1024 CTAs
    attn_matrix_mma_kernel<<<grid, THREADS, SMEM_TOTAL>>>(a, b, o);
}